// round 1
// baseline (speedup 1.0000x reference)
#include <cuda_runtime.h>
#include <mma.h>
#include <math.h>
#include <stdint.h>

using namespace nvcuda;

#define N_NODES 100000
#define N_EDGES 3200000
#define N_TOT   (N_EDGES + N_NODES)
#define F_IN    512
#define F_MID   256
#define F_OUT   64
#define K_STEPS 10

// ---------------- scratch (static __device__, no allocations) ----------------
__device__ float g_t[(size_t)N_NODES * F_MID];    // relu(x@W1+b1)
__device__ float g_h[(size_t)N_NODES * F_OUT];    // MLP output h
__device__ float g_z0[(size_t)N_NODES * F_OUT];   // ping
__device__ float g_z1[(size_t)N_NODES * F_OUT];   // pong
__device__ int   g_cnt[N_NODES];
__device__ int   g_off[N_NODES];
__device__ int   g_incl[N_NODES];
__device__ int   g_colptr[N_NODES + 1];
__device__ int   g_aux[128];
__device__ int   g_auxex[128];
__device__ float g_dinv[N_NODES];
__device__ int   g_erow[N_TOT];
__device__ float g_enorm[N_TOT];

// ---------------- CSR build ----------------
__global__ void k_init() {
    int i = blockIdx.x * blockDim.x + threadIdx.x;
    if (i < N_NODES) { g_cnt[i] = 1; g_off[i] = 0; }  // cnt starts at 1: self-loop
}

__global__ void k_count(const int* __restrict__ col) {
    int e = blockIdx.x * blockDim.x + threadIdx.x;
    if (e < N_EDGES) atomicAdd(&g_cnt[col[e]], 1);
}

__global__ void k_dinv() {
    int i = blockIdx.x * blockDim.x + threadIdx.x;
    if (i < N_NODES) g_dinv[i] = rsqrtf((float)g_cnt[i]);  // deg >= 1 always
}

__global__ void k_scan1() {
    __shared__ int s[1024];
    int i = blockIdx.x * 1024 + threadIdx.x;
    int v = (i < N_NODES) ? g_cnt[i] : 0;
    s[threadIdx.x] = v;
    __syncthreads();
    for (int d = 1; d < 1024; d <<= 1) {
        int t = (threadIdx.x >= d) ? s[threadIdx.x - d] : 0;
        __syncthreads();
        s[threadIdx.x] += t;
        __syncthreads();
    }
    if (i < N_NODES) g_incl[i] = s[threadIdx.x];
    if (threadIdx.x == 1023) g_aux[blockIdx.x] = s[1023];
}

__global__ void k_scanaux(int nb) {
    if (blockIdx.x == 0 && threadIdx.x == 0) {
        int run = 0;
        for (int b = 0; b < nb; b++) { g_auxex[b] = run; run += g_aux[b]; }
    }
}

__global__ void k_finalize() {
    int i = blockIdx.x * blockDim.x + threadIdx.x;
    if (i < N_NODES) {
        g_colptr[i + 1] = g_incl[i] + g_auxex[i >> 10];
        if (i == 0) g_colptr[0] = 0;
    }
}

__global__ void k_fill(const int* __restrict__ rowp, const int* __restrict__ colp) {
    int i = blockIdx.x * blockDim.x + threadIdx.x;
    if (i < N_TOT) {
        int r, c;
        if (i < N_EDGES) { r = rowp[i]; c = colp[i]; }
        else             { r = c = i - N_EDGES; }
        float nrm = g_dinv[r] * g_dinv[c];
        int idx = g_colptr[c] + atomicAdd(&g_off[c], 1);
        g_erow[idx] = r;
        g_enorm[idx] = nrm;
    }
}

// ---------------- TF32 wmma GEMM: C = act(A[M,K] @ B[K,N] + bias) ----------------
// Block tile 32x64, 4 warps, warp tile 16x32 (2x m16n16k8 frags). M=100000 % 32 == 0.
template <int KD, int ND, bool RELU>
__device__ __forceinline__ void gemm_core(const float* __restrict__ A,
                                          const float* __restrict__ B,
                                          const float* __restrict__ bias,
                                          float* __restrict__ C) {
    constexpr int BM = 32, BN = 64, BK = 16;
    __shared__ float As[BM][BK + 4];
    __shared__ float Bs[BK][BN + 4];
    __shared__ float Cs[BM][BN];
    const int tid = threadIdx.x;          // 128 threads
    const int warp = tid >> 5;
    const int wr = warp >> 1, wc = warp & 1;
    const int m0 = blockIdx.x * BM, n0 = blockIdx.y * BN;

    wmma::fragment<wmma::accumulator, 16, 16, 8, float> c0, c1;
    wmma::fill_fragment(c0, 0.f);
    wmma::fill_fragment(c1, 0.f);

    for (int k0 = 0; k0 < KD; k0 += BK) {
        // A tile: 32x16 = 128 float4, one per thread
        {
            int r = tid >> 2, c4 = (tid & 3) << 2;
            *(float4*)&As[r][c4] =
                *(const float4*)&A[(size_t)(m0 + r) * KD + k0 + c4];
        }
        // B tile: 16x64 = 256 float4, two per thread
        #pragma unroll
        for (int l = 0; l < 2; l++) {
            int idx = tid + l * 128;
            int br = idx >> 4, bc4 = (idx & 15) << 2;
            *(float4*)&Bs[br][bc4] =
                *(const float4*)&B[(size_t)(k0 + br) * ND + n0 + bc4];
        }
        __syncthreads();
        #pragma unroll
        for (int kk = 0; kk < BK; kk += 8) {
            wmma::fragment<wmma::matrix_a, 16, 16, 8, wmma::precision::tf32, wmma::row_major> a;
            wmma::fragment<wmma::matrix_b, 16, 16, 8, wmma::precision::tf32, wmma::row_major> b0f, b1f;
            wmma::load_matrix_sync(a,   &As[wr * 16][kk],        BK + 4);
            wmma::load_matrix_sync(b0f, &Bs[kk][wc * 32],        BN + 4);
            wmma::load_matrix_sync(b1f, &Bs[kk][wc * 32 + 16],   BN + 4);
            #pragma unroll
            for (int i = 0; i < a.num_elements; i++) a.x[i] = wmma::__float_to_tf32(a.x[i]);
            #pragma unroll
            for (int i = 0; i < b0f.num_elements; i++) {
                b0f.x[i] = wmma::__float_to_tf32(b0f.x[i]);
                b1f.x[i] = wmma::__float_to_tf32(b1f.x[i]);
            }
            wmma::mma_sync(c0, a, b0f, c0);
            wmma::mma_sync(c1, a, b1f, c1);
        }
        __syncthreads();
    }
    wmma::store_matrix_sync(&Cs[wr * 16][wc * 32],      c0, BN, wmma::mem_row_major);
    wmma::store_matrix_sync(&Cs[wr * 16][wc * 32 + 16], c1, BN, wmma::mem_row_major);
    __syncthreads();
    #pragma unroll
    for (int l = 0; l < 4; l++) {
        int idx = tid + l * 128;          // 512 float4 total
        int r = idx >> 4, c4 = (idx & 15) << 2;
        float4 v = *(float4*)&Cs[r][c4];
        float4 bb = *(const float4*)&bias[n0 + c4];
        v.x += bb.x; v.y += bb.y; v.z += bb.z; v.w += bb.w;
        if (RELU) {
            v.x = fmaxf(v.x, 0.f); v.y = fmaxf(v.y, 0.f);
            v.z = fmaxf(v.z, 0.f); v.w = fmaxf(v.w, 0.f);
        }
        *(float4*)&C[(size_t)(m0 + r) * ND + n0 + c4] = v;
    }
}

__global__ void k_gemm1(const float* __restrict__ x, const float* __restrict__ W1,
                        const float* __restrict__ b1) {
    gemm_core<F_IN, F_MID, true>(x, W1, b1, g_t);
}
__global__ void k_gemm2(const float* __restrict__ W2, const float* __restrict__ b2) {
    gemm_core<F_MID, F_OUT, false>(g_t, W2, b2, g_h);
}

// ---------------- APPNP propagation: z_out = 0.9 * (A_norm @ z_in) + 0.1 * h ----------------
// One 64-thread group (2 warps) per destination node; thread = feature.
__global__ void k_prop(int it) {
    const float* __restrict__ zin = (it == 0) ? g_h : ((it & 1) ? g_z0 : g_z1);
    float* __restrict__ zout = (it & 1) ? g_z1 : g_z0;
    int node = blockIdx.x * 4 + threadIdx.y;
    int f = threadIdx.x;
    if (node >= N_NODES) return;
    int s = g_colptr[node], e = g_colptr[node + 1];
    float acc = 0.f;
    int i = s;
    for (; i + 4 <= e; i += 4) {
        int r0 = g_erow[i],     r1 = g_erow[i + 1];
        int r2 = g_erow[i + 2], r3 = g_erow[i + 3];
        float w0 = g_enorm[i],     w1 = g_enorm[i + 1];
        float w2 = g_enorm[i + 2], w3 = g_enorm[i + 3];
        float a0 = zin[r0 * 64 + f];
        float a1 = zin[r1 * 64 + f];
        float a2 = zin[r2 * 64 + f];
        float a3 = zin[r3 * 64 + f];
        acc += w0 * a0; acc += w1 * a1; acc += w2 * a2; acc += w3 * a3;
    }
    for (; i < e; ++i) acc += g_enorm[i] * zin[g_erow[i] * 64 + f];
    zout[node * 64 + f] = 0.9f * acc + 0.1f * g_h[node * 64 + f];
}

// ---------------- log_softmax over 64 classes: one warp per node ----------------
__global__ void k_lsm(float* __restrict__ out) {
    int warp = threadIdx.x >> 5, lane = threadIdx.x & 31;
    int node = blockIdx.x * 8 + warp;
    if (node >= N_NODES) return;
    float2 v = *reinterpret_cast<const float2*>(&g_z1[node * 64 + lane * 2]);
    float m = fmaxf(v.x, v.y);
    #pragma unroll
    for (int d = 16; d > 0; d >>= 1) m = fmaxf(m, __shfl_xor_sync(0xffffffffu, m, d));
    float s = expf(v.x - m) + expf(v.y - m);
    #pragma unroll
    for (int d = 16; d > 0; d >>= 1) s += __shfl_xor_sync(0xffffffffu, s, d);
    float l = m + logf(s);
    float2 o; o.x = v.x - l; o.y = v.y - l;
    *reinterpret_cast<float2*>(&out[node * 64 + lane * 2]) = o;
}

// ---------------- launch ----------------
extern "C" void kernel_launch(void* const* d_in, const int* in_sizes, int n_in,
                              void* d_out, int out_size) {
    const float* x  = (const float*)d_in[0];
    const int*   ei = (const int*)d_in[1];
    const float* W1 = (const float*)d_in[2];
    const float* b1 = (const float*)d_in[3];
    const float* W2 = (const float*)d_in[4];
    const float* b2 = (const float*)d_in[5];
    float* out = (float*)d_out;

    const int* rowp = ei;            // edge_index[0] : source (gathered)
    const int* colp = ei + N_EDGES;  // edge_index[1] : destination (aggregated)

    // CSR-by-destination build
    k_init<<<(N_NODES + 255) / 256, 256>>>();
    k_count<<<(N_EDGES + 255) / 256, 256>>>(colp);
    k_dinv<<<(N_NODES + 255) / 256, 256>>>();
    int nb = (N_NODES + 1023) / 1024;
    k_scan1<<<nb, 1024>>>();
    k_scanaux<<<1, 32>>>(nb);
    k_finalize<<<(N_NODES + 255) / 256, 256>>>();
    k_fill<<<(N_TOT + 255) / 256, 256>>>(rowp, colp);

    // MLP (TF32 tensor cores)
    k_gemm1<<<dim3(N_NODES / 32, F_MID / 64), 128>>>(x, W1, b1);
    k_gemm2<<<dim3(N_NODES / 32, 1), 128>>>(W2, b2);

    // K propagation steps (gather-only, CSR)
    for (int it = 0; it < K_STEPS; ++it)
        k_prop<<<(N_NODES + 3) / 4, dim3(64, 4)>>>(it);

    // log_softmax
    k_lsm<<<(N_NODES + 7) / 8, 256>>>(out);
}

// round 2
// speedup vs baseline: 1.4856x; 1.4856x over previous
#include <cuda_runtime.h>
#include <cuda_fp16.h>
#include <mma.h>
#include <math.h>
#include <stdint.h>

using namespace nvcuda;

#define N_NODES 100000
#define N_PAD   (N_NODES + 64)
#define N_EDGES 3200000
#define N_TOT   (N_EDGES + N_NODES)
#define F_IN    512
#define F_MID   256
#define F_OUT   64
#define K_STEPS 10

// ---------------- scratch (static __device__, no allocations) ----------------
__device__ float   g_t[(size_t)N_PAD * F_MID];     // x@W1 (pre-bias, pre-relu)
__device__ float   g_h[(size_t)N_PAD * F_OUT];     // MLP output h (fp32)
__device__ __half2 g_hh[(size_t)N_PAD * 32];       // h in fp16 (gather source, iter 0)
__device__ __half2 g_zh0[(size_t)N_PAD * 32];      // ping (fp16)
__device__ __half2 g_zh1[(size_t)N_PAD * 32];      // pong (fp16)
__device__ int     g_cnt[N_NODES];
__device__ int     g_off[N_NODES];
__device__ int     g_incl[N_NODES];
__device__ int     g_colptr[N_NODES + 1];
__device__ int     g_aux[128];
__device__ int     g_auxex[128];
__device__ float   g_dinv[N_NODES];
__device__ int2    g_edge[N_TOT];                  // {src_row, norm-as-int}

// ---------------- CSR build ----------------
__global__ void k_init() {
    int i = blockIdx.x * blockDim.x + threadIdx.x;
    if (i < N_NODES) { g_cnt[i] = 1; g_off[i] = 0; }  // self-loop pre-counted
}

__global__ void k_count(const int* __restrict__ col) {
    int e = blockIdx.x * blockDim.x + threadIdx.x;
    if (e < N_EDGES) atomicAdd(&g_cnt[col[e]], 1);
}

__global__ void k_dinv() {
    int i = blockIdx.x * blockDim.x + threadIdx.x;
    if (i < N_NODES) g_dinv[i] = rsqrtf((float)g_cnt[i]);
}

__global__ void k_scan1() {
    __shared__ int s[1024];
    int i = blockIdx.x * 1024 + threadIdx.x;
    int v = (i < N_NODES) ? g_cnt[i] : 0;
    s[threadIdx.x] = v;
    __syncthreads();
    for (int d = 1; d < 1024; d <<= 1) {
        int t = (threadIdx.x >= d) ? s[threadIdx.x - d] : 0;
        __syncthreads();
        s[threadIdx.x] += t;
        __syncthreads();
    }
    if (i < N_NODES) g_incl[i] = s[threadIdx.x];
    if (threadIdx.x == 1023) g_aux[blockIdx.x] = s[1023];
}

__global__ void k_scanaux(int nb) {
    if (blockIdx.x == 0 && threadIdx.x == 0) {
        int run = 0;
        for (int b = 0; b < nb; b++) { g_auxex[b] = run; run += g_aux[b]; }
    }
}

__global__ void k_finalize() {
    int i = blockIdx.x * blockDim.x + threadIdx.x;
    if (i < N_NODES) {
        g_colptr[i + 1] = g_incl[i] + g_auxex[i >> 10];
        if (i == 0) g_colptr[0] = 0;
    }
}

__global__ void k_fill(const int* __restrict__ rowp, const int* __restrict__ colp) {
    int i = blockIdx.x * blockDim.x + threadIdx.x;
    if (i < N_TOT) {
        int r, c;
        if (i < N_EDGES) { r = rowp[i]; c = colp[i]; }
        else             { r = c = i - N_EDGES; }
        float nrm = g_dinv[r] * g_dinv[c];
        int idx = g_colptr[c] + atomicAdd(&g_off[c], 1);
        g_edge[idx] = make_int2(r, __float_as_int(nrm));
    }
}

// ---------------- GEMM1: g_t = x @ W1 (TF32, 64x128 tile, direct frag store) ----------------
__global__ void k_gemm1(const float* __restrict__ A, const float* __restrict__ B) {
    constexpr int BM = 64, BN = 128, BK = 16;
    __shared__ float As[BM][BK + 4];
    __shared__ float Bs[BK][BN + 4];
    const int tid = threadIdx.x;        // 256
    const int warp = tid >> 5;
    const int wr = warp >> 2, wc = warp & 3;   // 2 x 4 warps, 32x32 each
    const int m0 = blockIdx.x * BM, n0 = blockIdx.y * BN;

    wmma::fragment<wmma::accumulator, 16, 16, 8, float> c[2][2];
    #pragma unroll
    for (int i = 0; i < 2; i++)
        #pragma unroll
        for (int j = 0; j < 2; j++) wmma::fill_fragment(c[i][j], 0.f);

    for (int k0 = 0; k0 < F_IN; k0 += BK) {
        {   // A tile: 64x16 = 256 float4, 1 per thread (row-clamped for last block)
            int r = tid >> 2, c4 = (tid & 3) << 2;
            int gr = min(m0 + r, N_NODES - 1);
            *(float4*)&As[r][c4] = *(const float4*)&A[(size_t)gr * F_IN + k0 + c4];
        }
        #pragma unroll
        for (int l = 0; l < 2; l++) {   // B tile: 16x128 = 512 float4
            int idx = tid + l * 256;
            int br = idx >> 5, bc4 = (idx & 31) << 2;
            *(float4*)&Bs[br][bc4] = *(const float4*)&B[(size_t)(k0 + br) * F_MID + n0 + bc4];
        }
        __syncthreads();
        #pragma unroll
        for (int kk = 0; kk < BK; kk += 8) {
            wmma::fragment<wmma::matrix_a, 16, 16, 8, wmma::precision::tf32, wmma::row_major> a0, a1;
            wmma::fragment<wmma::matrix_b, 16, 16, 8, wmma::precision::tf32, wmma::row_major> b0, b1;
            wmma::load_matrix_sync(a0, &As[wr * 32][kk],      BK + 4);
            wmma::load_matrix_sync(a1, &As[wr * 32 + 16][kk], BK + 4);
            wmma::load_matrix_sync(b0, &Bs[kk][wc * 32],      BN + 4);
            wmma::load_matrix_sync(b1, &Bs[kk][wc * 32 + 16], BN + 4);
            #pragma unroll
            for (int i = 0; i < a0.num_elements; i++) {
                a0.x[i] = wmma::__float_to_tf32(a0.x[i]);
                a1.x[i] = wmma::__float_to_tf32(a1.x[i]);
            }
            #pragma unroll
            for (int i = 0; i < b0.num_elements; i++) {
                b0.x[i] = wmma::__float_to_tf32(b0.x[i]);
                b1.x[i] = wmma::__float_to_tf32(b1.x[i]);
            }
            wmma::mma_sync(c[0][0], a0, b0, c[0][0]);
            wmma::mma_sync(c[0][1], a0, b1, c[0][1]);
            wmma::mma_sync(c[1][0], a1, b0, c[1][0]);
            wmma::mma_sync(c[1][1], a1, b1, c[1][1]);
        }
        __syncthreads();
    }
    // Direct store to g_t (padded, no bounds issue)
    #pragma unroll
    for (int i = 0; i < 2; i++)
        #pragma unroll
        for (int j = 0; j < 2; j++)
            wmma::store_matrix_sync(
                &g_t[(size_t)(m0 + wr * 32 + i * 16) * F_MID + n0 + wc * 32 + j * 16],
                c[i][j], F_MID, wmma::mem_row_major);
}

// ---------------- GEMM2: h = relu(t + b1) @ W2 + b2 (bias1+relu fused into A load) ----------------
__global__ void k_gemm2(const float* __restrict__ B,
                        const float* __restrict__ b1, const float* __restrict__ b2) {
    constexpr int BM = 64, BN = 64, BK = 16;
    __shared__ float As[BM][BK + 4];
    __shared__ float Bs[BK][BN + 4];
    __shared__ float Cs[BM][BN + 4];
    const int tid = threadIdx.x;        // 128
    const int warp = tid >> 5;
    const int wr = warp >> 1, wc = warp & 1;   // 2 x 2 warps, 32x32 each
    const int m0 = blockIdx.x * BM;

    wmma::fragment<wmma::accumulator, 16, 16, 8, float> c[2][2];
    #pragma unroll
    for (int i = 0; i < 2; i++)
        #pragma unroll
        for (int j = 0; j < 2; j++) wmma::fill_fragment(c[i][j], 0.f);

    for (int k0 = 0; k0 < F_MID; k0 += BK) {
        #pragma unroll
        for (int l = 0; l < 2; l++) {   // A tile: 64x16 = 256 float4, relu(v + b1)
            int idx = tid + l * 128;
            int r = idx >> 2, c4 = (idx & 3) << 2;
            float4 v = *(const float4*)&g_t[(size_t)(m0 + r) * F_MID + k0 + c4];
            float4 bb = *(const float4*)&b1[k0 + c4];
            v.x = fmaxf(v.x + bb.x, 0.f); v.y = fmaxf(v.y + bb.y, 0.f);
            v.z = fmaxf(v.z + bb.z, 0.f); v.w = fmaxf(v.w + bb.w, 0.f);
            *(float4*)&As[r][c4] = v;
        }
        #pragma unroll
        for (int l = 0; l < 2; l++) {   // B tile: 16x64 = 256 float4
            int idx = tid + l * 128;
            int br = idx >> 4, bc4 = (idx & 15) << 2;
            *(float4*)&Bs[br][bc4] = *(const float4*)&B[(size_t)(k0 + br) * F_OUT + bc4];
        }
        __syncthreads();
        #pragma unroll
        for (int kk = 0; kk < BK; kk += 8) {
            wmma::fragment<wmma::matrix_a, 16, 16, 8, wmma::precision::tf32, wmma::row_major> a0, a1;
            wmma::fragment<wmma::matrix_b, 16, 16, 8, wmma::precision::tf32, wmma::row_major> b0, b1f;
            wmma::load_matrix_sync(a0, &As[wr * 32][kk],      BK + 4);
            wmma::load_matrix_sync(a1, &As[wr * 32 + 16][kk], BK + 4);
            wmma::load_matrix_sync(b0, &Bs[kk][wc * 32],      BN + 4);
            wmma::load_matrix_sync(b1f, &Bs[kk][wc * 32 + 16], BN + 4);
            #pragma unroll
            for (int i = 0; i < a0.num_elements; i++) {
                a0.x[i] = wmma::__float_to_tf32(a0.x[i]);
                a1.x[i] = wmma::__float_to_tf32(a1.x[i]);
            }
            #pragma unroll
            for (int i = 0; i < b0.num_elements; i++) {
                b0.x[i] = wmma::__float_to_tf32(b0.x[i]);
                b1f.x[i] = wmma::__float_to_tf32(b1f.x[i]);
            }
            wmma::mma_sync(c[0][0], a0, b0,  c[0][0]);
            wmma::mma_sync(c[0][1], a0, b1f, c[0][1]);
            wmma::mma_sync(c[1][0], a1, b0,  c[1][0]);
            wmma::mma_sync(c[1][1], a1, b1f, c[1][1]);
        }
        __syncthreads();
    }
    #pragma unroll
    for (int i = 0; i < 2; i++)
        #pragma unroll
        for (int j = 0; j < 2; j++)
            wmma::store_matrix_sync(&Cs[wr * 32 + i * 16][wc * 32 + j * 16],
                                    c[i][j], BN + 4, wmma::mem_row_major);
    __syncthreads();
    #pragma unroll
    for (int l = 0; l < 8; l++) {       // 64x64 = 1024 float4 / 128 thr
        int idx = tid + l * 128;
        int r = idx >> 4, c4 = (idx & 15) << 2;
        float4 v = *(float4*)&Cs[r][c4];
        float4 bb = *(const float4*)&b2[c4];
        v.x += bb.x; v.y += bb.y; v.z += bb.z; v.w += bb.w;
        size_t o = (size_t)(m0 + r) * F_OUT + c4;
        *(float4*)&g_h[o] = v;
        size_t oh = (size_t)(m0 + r) * 32 + (c4 >> 1);
        g_hh[oh]     = __floats2half2_rn(v.x, v.y);
        g_hh[oh + 1] = __floats2half2_rn(v.z, v.w);
    }
}

// ---------------- APPNP propagation (fp16 z, warp per node, fused lsm on last iter) ----------------
__global__ void k_prop(float* __restrict__ outF, int it) {
    const __half2* __restrict__ zin = (it == 0) ? g_hh : ((it & 1) ? g_zh0 : g_zh1);
    __half2* __restrict__ zout = (it & 1) ? g_zh1 : g_zh0;
    const int warp = threadIdx.x >> 5, lane = threadIdx.x & 31;
    const int node = blockIdx.x * 8 + warp;
    if (node >= N_NODES) return;
    const int s = g_colptr[node], e = g_colptr[node + 1];
    float ax = 0.f, ay = 0.f;
    int i = s;
    for (; i + 4 <= e; i += 4) {
        int2 e0 = g_edge[i],     e1 = g_edge[i + 1];
        int2 e2 = g_edge[i + 2], e3 = g_edge[i + 3];
        float2 f0 = __half22float2(zin[(size_t)e0.x * 32 + lane]);
        float2 f1 = __half22float2(zin[(size_t)e1.x * 32 + lane]);
        float2 f2 = __half22float2(zin[(size_t)e2.x * 32 + lane]);
        float2 f3 = __half22float2(zin[(size_t)e3.x * 32 + lane]);
        float w0 = __int_as_float(e0.y), w1 = __int_as_float(e1.y);
        float w2 = __int_as_float(e2.y), w3 = __int_as_float(e3.y);
        ax = fmaf(w0, f0.x, ax); ay = fmaf(w0, f0.y, ay);
        ax = fmaf(w1, f1.x, ax); ay = fmaf(w1, f1.y, ay);
        ax = fmaf(w2, f2.x, ax); ay = fmaf(w2, f2.y, ay);
        ax = fmaf(w3, f3.x, ax); ay = fmaf(w3, f3.y, ay);
    }
    for (; i < e; ++i) {
        int2 ed = g_edge[i];
        float2 f = __half22float2(zin[(size_t)ed.x * 32 + lane]);
        float w = __int_as_float(ed.y);
        ax = fmaf(w, f.x, ax); ay = fmaf(w, f.y, ay);
    }
    float2 h = *(const float2*)&g_h[(size_t)node * F_OUT + lane * 2];
    float ox = 0.9f * ax + 0.1f * h.x;
    float oy = 0.9f * ay + 0.1f * h.y;
    if (it != K_STEPS - 1) {
        zout[(size_t)node * 32 + lane] = __floats2half2_rn(ox, oy);
    } else {
        float m = fmaxf(ox, oy);
        #pragma unroll
        for (int d = 16; d > 0; d >>= 1) m = fmaxf(m, __shfl_xor_sync(0xffffffffu, m, d));
        float sm = expf(ox - m) + expf(oy - m);
        #pragma unroll
        for (int d = 16; d > 0; d >>= 1) sm += __shfl_xor_sync(0xffffffffu, sm, d);
        float l = m + logf(sm);
        float2 o; o.x = ox - l; o.y = oy - l;
        *(float2*)&outF[(size_t)node * F_OUT + lane * 2] = o;
    }
}

// ---------------- launch ----------------
extern "C" void kernel_launch(void* const* d_in, const int* in_sizes, int n_in,
                              void* d_out, int out_size) {
    const float* x  = (const float*)d_in[0];
    const int*   ei = (const int*)d_in[1];
    const float* W1 = (const float*)d_in[2];
    const float* b1 = (const float*)d_in[3];
    const float* W2 = (const float*)d_in[4];
    const float* b2 = (const float*)d_in[5];
    float* out = (float*)d_out;

    const int* rowp = ei;            // sources (gathered)
    const int* colp = ei + N_EDGES;  // destinations (aggregated)

    // CSR-by-destination build
    k_init<<<(N_NODES + 255) / 256, 256>>>();
    k_count<<<(N_EDGES + 255) / 256, 256>>>(colp);
    k_dinv<<<(N_NODES + 255) / 256, 256>>>();
    int nb = (N_NODES + 1023) / 1024;
    k_scan1<<<nb, 1024>>>();
    k_scanaux<<<1, 32>>>(nb);
    k_finalize<<<(N_NODES + 255) / 256, 256>>>();
    k_fill<<<(N_TOT + 255) / 256, 256>>>(rowp, colp);

    // MLP (TF32 tensor cores)
    int mb = (N_NODES + 63) / 64;    // 1563
    k_gemm1<<<dim3(mb, F_MID / 128), 256>>>(x, W1);
    k_gemm2<<<dim3(mb, 1), 128>>>(W2, b1, b2);

    // K propagation steps (gather-only, fp16 z)
    for (int it = 0; it < K_STEPS; ++it)
        k_prop<<<(N_NODES + 7) / 8, 256>>>(out, it);
}

// round 3
// speedup vs baseline: 1.8370x; 1.2365x over previous
#include <cuda_runtime.h>
#include <cuda_fp16.h>
#include <mma.h>
#include <math.h>
#include <stdint.h>

using namespace nvcuda;

#define N_NODES 100000
#define N_PAD   (N_NODES + 64)
#define N_EDGES 3200000
#define N_TOT   (N_EDGES + N_NODES)
#define F_IN    512
#define F_MID   256
#define F_OUT   64
#define K_STEPS 10

// ---------------- scratch ----------------
__device__ float   g_t[(size_t)N_PAD * F_MID];     // x@W1 (pre-bias/relu)
__device__ __half2 g_hh[(size_t)N_PAD * 32];       // h fp16 (unscaled)
__device__ __half2 g_y0[(size_t)N_PAD * 32];       // y = dinv*z ping
__device__ __half2 g_y1[(size_t)N_PAD * 32];       // pong
__device__ int     g_cnt[N_NODES];
__device__ int     g_off[N_NODES];
__device__ int     g_incl[N_NODES];
__device__ int     g_colptr[N_NODES + 1];
__device__ int     g_aux[128];
__device__ int     g_auxex[128];
__device__ float   g_dinv[N_NODES];
__device__ int     g_erow[N_TOT];                  // src row only (norm folded into y)

// ---------------- CSR build ----------------
__global__ void k_init() {
    int i = blockIdx.x * blockDim.x + threadIdx.x;
    if (i < N_NODES) { g_cnt[i] = 1; g_off[i] = 0; }
}
__global__ void k_count(const int* __restrict__ col) {
    int e = blockIdx.x * blockDim.x + threadIdx.x;
    if (e < N_EDGES) atomicAdd(&g_cnt[col[e]], 1);
}
__global__ void k_dinv() {
    int i = blockIdx.x * blockDim.x + threadIdx.x;
    if (i < N_NODES) g_dinv[i] = rsqrtf((float)g_cnt[i]);
}
__global__ void k_scan1() {
    __shared__ int s[1024];
    int i = blockIdx.x * 1024 + threadIdx.x;
    int v = (i < N_NODES) ? g_cnt[i] : 0;
    s[threadIdx.x] = v;
    __syncthreads();
    for (int d = 1; d < 1024; d <<= 1) {
        int t = (threadIdx.x >= d) ? s[threadIdx.x - d] : 0;
        __syncthreads();
        s[threadIdx.x] += t;
        __syncthreads();
    }
    if (i < N_NODES) g_incl[i] = s[threadIdx.x];
    if (threadIdx.x == 1023) g_aux[blockIdx.x] = s[1023];
}
__global__ void k_scanaux(int nb) {
    if (threadIdx.x == 0) {
        int run = 0;
        for (int b = 0; b < nb; b++) { g_auxex[b] = run; run += g_aux[b]; }
    }
}
__global__ void k_finalize() {
    int i = blockIdx.x * blockDim.x + threadIdx.x;
    if (i < N_NODES) {
        g_colptr[i + 1] = g_incl[i] + g_auxex[i >> 10];
        if (i == 0) g_colptr[0] = 0;
    }
}
__global__ void k_fill(const int* __restrict__ rowp, const int* __restrict__ colp) {
    int i = blockIdx.x * blockDim.x + threadIdx.x;
    if (i < N_TOT) {
        int r, c;
        if (i < N_EDGES) { r = rowp[i]; c = colp[i]; }
        else             { r = c = i - N_EDGES; }
        int idx = g_colptr[c] + atomicAdd(&g_off[c], 1);
        g_erow[idx] = r;
    }
}

// ---------------- GEMM1: g_t = x @ W1 (TF32; conversion at smem fill) ----------------
__global__ void k_gemm1(const float* __restrict__ A, const float* __restrict__ B) {
    constexpr int BM = 64, BN = 128, BK = 16;
    __shared__ float As[BM][BK + 4];
    __shared__ float Bs[BK][BN + 4];
    const int tid = threadIdx.x;        // 256
    const int warp = tid >> 5;
    const int wr = warp >> 2, wc = warp & 3;
    const int m0 = blockIdx.x * BM, n0 = blockIdx.y * BN;

    wmma::fragment<wmma::accumulator, 16, 16, 8, float> c[2][2];
    #pragma unroll
    for (int i = 0; i < 2; i++)
        #pragma unroll
        for (int j = 0; j < 2; j++) wmma::fill_fragment(c[i][j], 0.f);

    for (int k0 = 0; k0 < F_IN; k0 += BK) {
        {
            int r = tid >> 2, c4 = (tid & 3) << 2;
            int gr = min(m0 + r, N_NODES - 1);
            float4 v = *(const float4*)&A[(size_t)gr * F_IN + k0 + c4];
            v.x = wmma::__float_to_tf32(v.x); v.y = wmma::__float_to_tf32(v.y);
            v.z = wmma::__float_to_tf32(v.z); v.w = wmma::__float_to_tf32(v.w);
            *(float4*)&As[r][c4] = v;
        }
        #pragma unroll
        for (int l = 0; l < 2; l++) {
            int idx = tid + l * 256;
            int br = idx >> 5, bc4 = (idx & 31) << 2;
            float4 v = *(const float4*)&B[(size_t)(k0 + br) * F_MID + n0 + bc4];
            v.x = wmma::__float_to_tf32(v.x); v.y = wmma::__float_to_tf32(v.y);
            v.z = wmma::__float_to_tf32(v.z); v.w = wmma::__float_to_tf32(v.w);
            *(float4*)&Bs[br][bc4] = v;
        }
        __syncthreads();
        #pragma unroll
        for (int kk = 0; kk < BK; kk += 8) {
            wmma::fragment<wmma::matrix_a, 16, 16, 8, wmma::precision::tf32, wmma::row_major> a0, a1;
            wmma::fragment<wmma::matrix_b, 16, 16, 8, wmma::precision::tf32, wmma::row_major> b0, b1;
            wmma::load_matrix_sync(a0, &As[wr * 32][kk],      BK + 4);
            wmma::load_matrix_sync(a1, &As[wr * 32 + 16][kk], BK + 4);
            wmma::load_matrix_sync(b0, &Bs[kk][wc * 32],      BN + 4);
            wmma::load_matrix_sync(b1, &Bs[kk][wc * 32 + 16], BN + 4);
            wmma::mma_sync(c[0][0], a0, b0, c[0][0]);
            wmma::mma_sync(c[0][1], a0, b1, c[0][1]);
            wmma::mma_sync(c[1][0], a1, b0, c[1][0]);
            wmma::mma_sync(c[1][1], a1, b1, c[1][1]);
        }
        __syncthreads();
    }
    #pragma unroll
    for (int i = 0; i < 2; i++)
        #pragma unroll
        for (int j = 0; j < 2; j++)
            wmma::store_matrix_sync(
                &g_t[(size_t)(m0 + wr * 32 + i * 16) * F_MID + n0 + wc * 32 + j * 16],
                c[i][j], F_MID, wmma::mem_row_major);
}

// ---------------- GEMM2: h = relu(t+b1) @ W2 + b2 ; writes fp16 h and y0 = dinv*h ----------------
__global__ void k_gemm2(const float* __restrict__ B,
                        const float* __restrict__ b1, const float* __restrict__ b2) {
    constexpr int BM = 64, BN = 64, BK = 16;
    __shared__ float As[BM][BK + 4];
    __shared__ float Bs[BK][BN + 4];
    __shared__ float Cs[BM][BN + 4];
    const int tid = threadIdx.x;        // 128
    const int warp = tid >> 5;
    const int wr = warp >> 1, wc = warp & 1;
    const int m0 = blockIdx.x * BM;

    wmma::fragment<wmma::accumulator, 16, 16, 8, float> c[2][2];
    #pragma unroll
    for (int i = 0; i < 2; i++)
        #pragma unroll
        for (int j = 0; j < 2; j++) wmma::fill_fragment(c[i][j], 0.f);

    for (int k0 = 0; k0 < F_MID; k0 += BK) {
        #pragma unroll
        for (int l = 0; l < 2; l++) {
            int idx = tid + l * 128;
            int r = idx >> 2, c4 = (idx & 3) << 2;
            float4 v = *(const float4*)&g_t[(size_t)(m0 + r) * F_MID + k0 + c4];
            float4 bb = *(const float4*)&b1[k0 + c4];
            v.x = wmma::__float_to_tf32(fmaxf(v.x + bb.x, 0.f));
            v.y = wmma::__float_to_tf32(fmaxf(v.y + bb.y, 0.f));
            v.z = wmma::__float_to_tf32(fmaxf(v.z + bb.z, 0.f));
            v.w = wmma::__float_to_tf32(fmaxf(v.w + bb.w, 0.f));
            *(float4*)&As[r][c4] = v;
        }
        #pragma unroll
        for (int l = 0; l < 2; l++) {
            int idx = tid + l * 128;
            int br = idx >> 4, bc4 = (idx & 15) << 2;
            float4 v = *(const float4*)&B[(size_t)(k0 + br) * F_OUT + bc4];
            v.x = wmma::__float_to_tf32(v.x); v.y = wmma::__float_to_tf32(v.y);
            v.z = wmma::__float_to_tf32(v.z); v.w = wmma::__float_to_tf32(v.w);
            *(float4*)&Bs[br][bc4] = v;
        }
        __syncthreads();
        #pragma unroll
        for (int kk = 0; kk < BK; kk += 8) {
            wmma::fragment<wmma::matrix_a, 16, 16, 8, wmma::precision::tf32, wmma::row_major> a0, a1;
            wmma::fragment<wmma::matrix_b, 16, 16, 8, wmma::precision::tf32, wmma::row_major> b0, b1f;
            wmma::load_matrix_sync(a0, &As[wr * 32][kk],      BK + 4);
            wmma::load_matrix_sync(a1, &As[wr * 32 + 16][kk], BK + 4);
            wmma::load_matrix_sync(b0, &Bs[kk][wc * 32],      BN + 4);
            wmma::load_matrix_sync(b1f, &Bs[kk][wc * 32 + 16], BN + 4);
            wmma::mma_sync(c[0][0], a0, b0,  c[0][0]);
            wmma::mma_sync(c[0][1], a0, b1f, c[0][1]);
            wmma::mma_sync(c[1][0], a1, b0,  c[1][0]);
            wmma::mma_sync(c[1][1], a1, b1f, c[1][1]);
        }
        __syncthreads();
    }
    #pragma unroll
    for (int i = 0; i < 2; i++)
        #pragma unroll
        for (int j = 0; j < 2; j++)
            wmma::store_matrix_sync(&Cs[wr * 32 + i * 16][wc * 32 + j * 16],
                                    c[i][j], BN + 4, wmma::mem_row_major);
    __syncthreads();
    #pragma unroll
    for (int l = 0; l < 8; l++) {
        int idx = tid + l * 128;
        int r = idx >> 4, c4 = (idx & 15) << 2;
        float4 v = *(float4*)&Cs[r][c4];
        float4 bb = *(const float4*)&b2[c4];
        v.x += bb.x; v.y += bb.y; v.z += bb.z; v.w += bb.w;
        int row = m0 + r;
        float di = (row < N_NODES) ? g_dinv[row] : 0.f;
        size_t oh = (size_t)row * 32 + (c4 >> 1);
        g_hh[oh]     = __floats2half2_rn(v.x, v.y);
        g_hh[oh + 1] = __floats2half2_rn(v.z, v.w);
        g_y0[oh]     = __floats2half2_rn(di * v.x, di * v.y);
        g_y0[oh + 1] = __floats2half2_rn(di * v.z, di * v.w);
    }
}

// ---------------- APPNP propagation ----------------
// Warp per node. lane = 8*g + k : g = edge-in-group (4 edges/load), k = feature octet.
// One LDG.128 gathers 4 edges x 16B (8 features) per lane-group -> 512B/instr.
__device__ __forceinline__ void acc8(float2& a0, float2& a1, float2& a2, float2& a3,
                                     const __half2* __restrict__ zin, int r, int k) {
    float4 v = *(const float4*)&zin[(size_t)r * 32 + k * 4];
    const __half2* hp = (const __half2*)&v;
    float2 t0 = __half22float2(hp[0]);
    float2 t1 = __half22float2(hp[1]);
    float2 t2 = __half22float2(hp[2]);
    float2 t3 = __half22float2(hp[3]);
    a0.x += t0.x; a0.y += t0.y;
    a1.x += t1.x; a1.y += t1.y;
    a2.x += t2.x; a2.y += t2.y;
    a3.x += t3.x; a3.y += t3.y;
}

__global__ void k_prop(float* __restrict__ outF, int it) {
    const __half2* __restrict__ zin = (it & 1) ? g_y1 : g_y0;
    __half2* __restrict__ zout = (it & 1) ? g_y0 : g_y1;
    const int warp = threadIdx.x >> 5, lane = threadIdx.x & 31;
    const int node = blockIdx.x * 8 + warp;
    if (node >= N_NODES) return;
    const int g = lane >> 3, k = lane & 7;
    const int s = g_colptr[node], e = g_colptr[node + 1];

    float2 a0 = {0.f, 0.f}, a1 = {0.f, 0.f}, a2 = {0.f, 0.f}, a3 = {0.f, 0.f};
    int i = s + g;
    while (i + 4 < e) {                       // two independent gathers in flight
        int r0 = g_erow[i];
        int r1 = g_erow[i + 4];
        acc8(a0, a1, a2, a3, zin, r0, k);
        acc8(a0, a1, a2, a3, zin, r1, k);
        i += 8;
    }
    if (i < e) {
        int r0 = g_erow[i];
        acc8(a0, a1, a2, a3, zin, r0, k);
    }
    // reduce across the 4 lane-groups (same k, different g)
    #pragma unroll
    for (int d = 8; d <= 16; d <<= 1) {
        a0.x += __shfl_xor_sync(0xffffffffu, a0.x, d);
        a0.y += __shfl_xor_sync(0xffffffffu, a0.y, d);
        a1.x += __shfl_xor_sync(0xffffffffu, a1.x, d);
        a1.y += __shfl_xor_sync(0xffffffffu, a1.y, d);
        a2.x += __shfl_xor_sync(0xffffffffu, a2.x, d);
        a2.y += __shfl_xor_sync(0xffffffffu, a2.y, d);
        a3.x += __shfl_xor_sync(0xffffffffu, a3.x, d);
        a3.y += __shfl_xor_sync(0xffffffffu, a3.y, d);
    }
    const float dc = g_dinv[node];
    float4 hv = *(const float4*)&g_hh[(size_t)node * 32 + k * 4];
    const __half2* hp = (const __half2*)&hv;
    float2 h0 = __half22float2(hp[0]), h1 = __half22float2(hp[1]);
    float2 h2 = __half22float2(hp[2]), h3 = __half22float2(hp[3]);
    const float w = 0.9f * dc;
    float z0x = w * a0.x + 0.1f * h0.x, z0y = w * a0.y + 0.1f * h0.y;
    float z1x = w * a1.x + 0.1f * h1.x, z1y = w * a1.y + 0.1f * h1.y;
    float z2x = w * a2.x + 0.1f * h2.x, z2y = w * a2.y + 0.1f * h2.y;
    float z3x = w * a3.x + 0.1f * h3.x, z3y = w * a3.y + 0.1f * h3.y;

    if (it != K_STEPS - 1) {
        if (g == 0) {
            __half2 o0 = __floats2half2_rn(dc * z0x, dc * z0y);
            __half2 o1 = __floats2half2_rn(dc * z1x, dc * z1y);
            __half2 o2 = __floats2half2_rn(dc * z2x, dc * z2y);
            __half2 o3 = __floats2half2_rn(dc * z3x, dc * z3y);
            uint4 pk;
            pk.x = *(unsigned*)&o0; pk.y = *(unsigned*)&o1;
            pk.z = *(unsigned*)&o2; pk.w = *(unsigned*)&o3;
            *(uint4*)&zout[(size_t)node * 32 + k * 4] = pk;
        }
    } else {
        // fused log_softmax over 64 classes
        float m = fmaxf(fmaxf(fmaxf(z0x, z0y), fmaxf(z1x, z1y)),
                        fmaxf(fmaxf(z2x, z2y), fmaxf(z3x, z3y)));
        #pragma unroll
        for (int d = 1; d <= 4; d <<= 1) m = fmaxf(m, __shfl_xor_sync(0xffffffffu, m, d));
        float sm = __expf(z0x - m) + __expf(z0y - m) + __expf(z1x - m) + __expf(z1y - m)
                 + __expf(z2x - m) + __expf(z2y - m) + __expf(z3x - m) + __expf(z3y - m);
        #pragma unroll
        for (int d = 1; d <= 4; d <<= 1) sm += __shfl_xor_sync(0xffffffffu, sm, d);
        float l = m + __logf(sm);
        if (g == 0) {
            float4 o;
            o.x = z0x - l; o.y = z0y - l; o.z = z1x - l; o.w = z1y - l;
            *(float4*)&outF[(size_t)node * F_OUT + k * 8] = o;
            o.x = z2x - l; o.y = z2y - l; o.z = z3x - l; o.w = z3y - l;
            *(float4*)&outF[(size_t)node * F_OUT + k * 8 + 4] = o;
        }
    }
}

// ---------------- launch ----------------
extern "C" void kernel_launch(void* const* d_in, const int* in_sizes, int n_in,
                              void* d_out, int out_size) {
    const float* x  = (const float*)d_in[0];
    const int*   ei = (const int*)d_in[1];
    const float* W1 = (const float*)d_in[2];
    const float* b1 = (const float*)d_in[3];
    const float* W2 = (const float*)d_in[4];
    const float* b2 = (const float*)d_in[5];
    float* out = (float*)d_out;

    const int* rowp = ei;
    const int* colp = ei + N_EDGES;

    k_init<<<(N_NODES + 255) / 256, 256>>>();
    k_count<<<(N_EDGES + 255) / 256, 256>>>(colp);
    k_dinv<<<(N_NODES + 255) / 256, 256>>>();
    int nb = (N_NODES + 1023) / 1024;
    k_scan1<<<nb, 1024>>>();
    k_scanaux<<<1, 32>>>(nb);
    k_finalize<<<(N_NODES + 255) / 256, 256>>>();
    k_fill<<<(N_TOT + 255) / 256, 256>>>(rowp, colp);

    int mb = (N_NODES + 63) / 64;
    k_gemm1<<<dim3(mb, F_MID / 128), 256>>>(x, W1);
    k_gemm2<<<dim3(mb, 1), 128>>>(W2, b1, b2);

    for (int it = 0; it < K_STEPS; ++it)
        k_prop<<<(N_NODES + 7) / 8, 256>>>(out, it);
}